// round 14
// baseline (speedup 1.0000x reference)
#include <cuda_runtime.h>
#include <cuda_bf16.h>
#include <stdint.h>

#define SEQ 2048
#define DIM 128
#define MT  128          // q rows per CTA
#define NT  128          // keys per tile
#define NTILES (SEQ / NT)
#define QBLKS (SEQ / MT)
#define RS  136          // smem bf16 row stride (padding: conflict-free ldmatrix)

#define TILE_B   (MT * RS * 2)        // 34816 bytes per bf16 tile
#define OFF_AHI  0
#define OFF_ALO  (TILE_B)
#define OFF_BHI  (2 * TILE_B)
#define OFF_BLO  (3 * TILE_B)
#define OFF_SM   (4 * TILE_B)         // k1: statm[128]
#define OFF_SL   (OFF_SM + 512)       // k1: statl[128]
#define OFF_BM   (OFF_SL + 512)       // k1: new-max broadcast[128]
#define OFF_RED  (OFF_BM + 512)       // k1: red[4][128]
#define SMEM1    (OFF_RED + 2048)     // 142848
#define OFF_FAC  (4 * TILE_B)         // k2: fac[NTILES][128]
#define SMEM2    (OFF_FAC + NTILES * MT * 4)   // 139264 + 8192

#define MAXB 32
__device__ float g_stats[MAXB * SEQ * 2];                  // per row: {m, 1/l}
__device__ float g_tilem[MAXB * QBLKS * NTILES * MT];      // running max at tile t

// ---------------------------------------------------------------------------
__device__ __forceinline__ uint32_t smem_u32(const void* p) {
    uint32_t a;
    asm("{ .reg .u64 t; cvta.to.shared.u64 t, %1; cvt.u32.u64 %0, t; }" : "=r"(a) : "l"(p));
    return a;
}

__device__ __forceinline__ void ldsm4(uint32_t* r, uint32_t addr) {
    asm volatile("ldmatrix.sync.aligned.m8n8.x4.shared.b16 {%0,%1,%2,%3}, [%4];"
        : "=r"(r[0]), "=r"(r[1]), "=r"(r[2]), "=r"(r[3]) : "r"(addr));
}
__device__ __forceinline__ void ldsm4t(uint32_t* r, uint32_t addr) {
    asm volatile("ldmatrix.sync.aligned.m8n8.x4.trans.shared.b16 {%0,%1,%2,%3}, [%4];"
        : "=r"(r[0]), "=r"(r[1]), "=r"(r[2]), "=r"(r[3]) : "r"(addr));
}
__device__ __forceinline__ void mma16816(float* c, const uint32_t* a,
                                         uint32_t b0, uint32_t b1) {
    asm volatile(
        "mma.sync.aligned.m16n8k16.row.col.f32.bf16.bf16.f32 "
        "{%0,%1,%2,%3}, {%4,%5,%6,%7}, {%8,%9}, {%0,%1,%2,%3};"
        : "+f"(c[0]), "+f"(c[1]), "+f"(c[2]), "+f"(c[3])
        : "r"(a[0]), "r"(a[1]), "r"(a[2]), "r"(a[3]), "r"(b0), "r"(b1));
}

// split f32 pair into bf16 hi/lo pairs at element offset eoff (even)
__device__ __forceinline__ void split2(char* hi, char* lo, int eoff,
                                       float f0, float f1) {
    __nv_bfloat16 h0 = __float2bfloat16(f0);
    __nv_bfloat16 h1 = __float2bfloat16(f1);
    __nv_bfloat162 hp; hp.x = h0; hp.y = h1;
    __nv_bfloat162 lp;
    lp.x = __float2bfloat16(f0 - __bfloat162float(h0));
    lp.y = __float2bfloat16(f1 - __bfloat162float(h1));
    *reinterpret_cast<__nv_bfloat162*>(hi + 2 * eoff) = hp;
    *reinterpret_cast<__nv_bfloat162*>(lo + 2 * eoff) = lp;
}

// ===========================================================================
// Kernel 1: scores (HMMA, 3-term split); stores e = exp(s - m_t) to attn buf
// plus per-(row,tile) running max m_t and final (m, 1/l) stats.
// ===========================================================================
__global__ void __launch_bounds__(512, 1) k1_scores(
    const float* __restrict__ Q, const float* __restrict__ K,
    float* __restrict__ attn)
{
    extern __shared__ char sm[];
    const uint32_t sb = smem_u32(sm);
    char* AHI = sm + OFF_AHI; char* ALO = sm + OFF_ALO;
    char* BHI = sm + OFF_BHI; char* BLO = sm + OFF_BLO;
    float* statm = (float*)(sm + OFF_SM);
    float* statl = (float*)(sm + OFF_SL);
    float* bm    = (float*)(sm + OFF_BM);
    float* red   = (float*)(sm + OFF_RED);

    const int tid  = threadIdx.x;
    const int lane = tid & 31;
    const int w    = tid >> 5;
    const int wm   = w >> 2, wn = w & 3;
    const int b    = blockIdx.y;
    const int q0   = blockIdx.x * MT;
    const float scale = 0.08838834764831845f;   // 1/sqrt(128)

    const int aoff = (lane & 15) * RS + ((lane & 16) >> 1);                  // A
    const int boff = ((lane & 7) + ((lane & 16) >> 1)) * RS + (lane & 8);    // B (K)

    // Q tile -> scaled bf16 hi/lo
    const float* Qg = Q + ((size_t)b * SEQ + q0) * DIM;
    for (int pi = tid; pi < MT * DIM / 2; pi += 512) {
        int r = pi >> 6, c2 = (pi & 63) * 2;
        float2 f = *(const float2*)(Qg + r * DIM + c2);
        split2(AHI, ALO, r * RS + c2, f.x * scale, f.y * scale);
    }
    if (tid < MT) { statm[tid] = -1e30f; statl[tid] = 0.f; }

    float* attnBase = attn + ((size_t)b * SEQ + q0) * SEQ;
    const float* Kg = K + (size_t)b * SEQ * DIM;
    float* tmBase = g_tilem + ((size_t)(b * QBLKS + blockIdx.x) * NTILES) * MT;

    for (int t = 0; t < NTILES; t++) {
        const int k0 = t * NT;
        __syncthreads();                       // B smem + stats reuse
        for (int pi = tid; pi < NT * DIM / 2; pi += 512) {
            int r = pi >> 6, c2 = (pi & 63) * 2;
            float2 f = *(const float2*)(Kg + (size_t)(k0 + r) * DIM + c2);
            split2(BHI, BLO, r * RS + c2, f.x, f.y);
        }
        __syncthreads();

        float c[2][4][4];
        #pragma unroll
        for (int mi = 0; mi < 2; mi++)
            #pragma unroll
            for (int ni = 0; ni < 4; ni++)
                #pragma unroll
                for (int j = 0; j < 4; j++) c[mi][ni][j] = 0.f;

        #pragma unroll
        for (int ks = 0; ks < 8; ks++) {
            const int k = ks * 16;
            uint32_t qh[2][4], ql[2][4], kh[2][4], kl[2][4];
            #pragma unroll
            for (int mi = 0; mi < 2; mi++) {
                int e = (wm * 32 + mi * 16) * RS + k + aoff;
                ldsm4(qh[mi], sb + OFF_AHI + 2 * e);
                ldsm4(ql[mi], sb + OFF_ALO + 2 * e);
            }
            #pragma unroll
            for (int g = 0; g < 2; g++) {
                int e = (wn * 32 + g * 16) * RS + k + boff;
                ldsm4(kh[g], sb + OFF_BHI + 2 * e);
                ldsm4(kl[g], sb + OFF_BLO + 2 * e);
            }
            #pragma unroll
            for (int mi = 0; mi < 2; mi++)
                #pragma unroll
                for (int ni = 0; ni < 4; ni++) {
                    int g = ni >> 1, ix = (ni & 1) * 2;
                    mma16816(c[mi][ni], qh[mi], kh[g][ix], kh[g][ix + 1]);
                    mma16816(c[mi][ni], qh[mi], kl[g][ix], kl[g][ix + 1]);
                    mma16816(c[mi][ni], ql[mi], kh[g][ix], kh[g][ix + 1]);
                }
        }

        // ---- epilogue: tile max -> e = exp(s - m_t) -> store e + sumexp ----
        const int t4 = lane >> 2, q4 = lane & 3;
        #pragma unroll
        for (int mi = 0; mi < 2; mi++) {
            int rA = wm * 32 + mi * 16 + t4;
            float mA = -1e30f, mB = -1e30f;
            #pragma unroll
            for (int ni = 0; ni < 4; ni++) {
                mA = fmaxf(mA, fmaxf(c[mi][ni][0], c[mi][ni][1]));
                mB = fmaxf(mB, fmaxf(c[mi][ni][2], c[mi][ni][3]));
            }
            mA = fmaxf(mA, __shfl_xor_sync(0xffffffffu, mA, 1));
            mA = fmaxf(mA, __shfl_xor_sync(0xffffffffu, mA, 2));
            mB = fmaxf(mB, __shfl_xor_sync(0xffffffffu, mB, 1));
            mB = fmaxf(mB, __shfl_xor_sync(0xffffffffu, mB, 2));
            if (q4 == 0) { red[wn * 128 + rA] = mA; red[wn * 128 + rA + 8] = mB; }
        }
        __syncthreads();
        if (tid < MT) {
            float mt = fmaxf(fmaxf(red[tid], red[128 + tid]),
                             fmaxf(red[256 + tid], red[384 + tid]));
            float mnew = fmaxf(statm[tid], mt);
            bm[tid] = mnew;
            tmBase[(size_t)t * MT + tid] = mnew;   // persist running max at tile t
        }
        __syncthreads();
        #pragma unroll
        for (int mi = 0; mi < 2; mi++) {
            int rA = wm * 32 + mi * 16 + t4;
            float mA = bm[rA], mB = bm[rA + 8];
            float sA = 0.f, sB = 0.f;
            #pragma unroll
            for (int ni = 0; ni < 4; ni++) {
                float e0 = __expf(c[mi][ni][0] - mA);
                float e1 = __expf(c[mi][ni][1] - mA);
                float e2 = __expf(c[mi][ni][2] - mB);
                float e3 = __expf(c[mi][ni][3] - mB);
                int col = k0 + wn * 32 + ni * 8 + 2 * q4;
                *(float2*)(attnBase + (size_t)rA * SEQ + col)       = make_float2(e0, e1);
                *(float2*)(attnBase + (size_t)(rA + 8) * SEQ + col) = make_float2(e2, e3);
                sA += e0 + e1;
                sB += e2 + e3;
            }
            sA += __shfl_xor_sync(0xffffffffu, sA, 1);
            sA += __shfl_xor_sync(0xffffffffu, sA, 2);
            sB += __shfl_xor_sync(0xffffffffu, sB, 1);
            sB += __shfl_xor_sync(0xffffffffu, sB, 2);
            if (q4 == 0) { red[wn * 128 + rA] = sA; red[wn * 128 + rA + 8] = sB; }
        }
        __syncthreads();
        if (tid < MT) {
            float mold = statm[tid], mnew = bm[tid];
            float s = red[tid] + red[128 + tid] + red[256 + tid] + red[384 + tid];
            statl[tid] = statl[tid] * __expf(mold - mnew) + s;
            statm[tid] = mnew;
        }
    }

    __syncthreads();
    if (tid < MT) {
        int row = b * SEQ + q0 + tid;
        g_stats[row * 2]     = statm[tid];
        g_stats[row * 2 + 1] = 1.f / statl[tid];
    }
}

// ===========================================================================
// Kernel 2: p = e * fac[row][tile] -> final attention; ctx = P @ V (HMMA)
// fac precomputed once: exp(m_t - m) / l  (2048 exps per CTA total)
// ===========================================================================
__global__ void __launch_bounds__(512, 1) k2_context(
    const float* __restrict__ V, float* __restrict__ attn,
    float* __restrict__ ctx)
{
    extern __shared__ char sm[];
    const uint32_t sb = smem_u32(sm);
    char* PHI = sm + OFF_AHI; char* PLO = sm + OFF_ALO;
    char* VHI = sm + OFF_BHI; char* VLO = sm + OFF_BLO;
    float* fac = (float*)(sm + OFF_FAC);       // [NTILES][MT]

    const int tid  = threadIdx.x;
    const int lane = tid & 31;
    const int w    = tid >> 5;
    const int wm   = w >> 2, wn = w & 3;
    const int b    = blockIdx.y;
    const int q0   = blockIdx.x * MT;

    const int aoff = (lane & 15) * RS + ((lane & 16) >> 1);                 // A (P)
    const int toff = ((lane & 7) + (lane & 8)) * RS + ((lane & 16) >> 1);   // B trans (V)

    // precompute all per-(tile,row) rescale factors
    const float* tmBase = g_tilem + ((size_t)(b * QBLKS + blockIdx.x) * NTILES) * MT;
    for (int i = tid; i < NTILES * MT; i += 512) {
        int t = i >> 7, r = i & (MT - 1);
        int row = b * SEQ + q0 + r;
        float m  = g_stats[row * 2];
        float il = g_stats[row * 2 + 1];
        fac[i] = __expf(tmBase[(size_t)t * MT + r] - m) * il;
    }

    float* attnBase = attn + ((size_t)b * SEQ + q0) * SEQ;
    const float* Vg = V + (size_t)b * SEQ * DIM;

    float c[2][4][4];
    #pragma unroll
    for (int mi = 0; mi < 2; mi++)
        #pragma unroll
        for (int ni = 0; ni < 4; ni++)
            #pragma unroll
            for (int j = 0; j < 4; j++) c[mi][ni][j] = 0.f;

    for (int t = 0; t < NTILES; t++) {
        const int k0 = t * NT;
        __syncthreads();                       // smem tile reuse (+ fac visible)
        const float* facT = fac + t * MT;
        // P: e -> p (final attn output) + split smem  (no exp here)
        for (int pi = tid; pi < MT * NT / 2; pi += 512) {
            int r = pi >> 6, c2 = (pi & 63) * 2;
            float* ap = attnBase + (size_t)r * SEQ + k0 + c2;
            float2 e = *(const float2*)ap;
            float f = facT[r];
            float p0 = e.x * f;
            float p1 = e.y * f;
            *(float2*)ap = make_float2(p0, p1);
            split2(PHI, PLO, r * RS + c2, p0, p1);
        }
        // V tile [key][d] -> bf16 hi/lo
        for (int pi = tid; pi < NT * DIM / 2; pi += 512) {
            int r = pi >> 6, c2 = (pi & 63) * 2;
            float2 f = *(const float2*)(Vg + (size_t)(k0 + r) * DIM + c2);
            split2(VHI, VLO, r * RS + c2, f.x, f.y);
        }
        __syncthreads();

        #pragma unroll
        for (int ks = 0; ks < 8; ks++) {
            const int k = ks * 16;
            uint32_t ph[2][4], pl[2][4], vh[2][4], vl[2][4];
            #pragma unroll
            for (int mi = 0; mi < 2; mi++) {
                int e = (wm * 32 + mi * 16) * RS + k + aoff;
                ldsm4(ph[mi], sb + OFF_AHI + 2 * e);
                ldsm4(pl[mi], sb + OFF_ALO + 2 * e);
            }
            #pragma unroll
            for (int g = 0; g < 2; g++) {
                int e = k * RS + (wn * 32 + g * 16) + toff;
                ldsm4t(vh[g], sb + OFF_BHI + 2 * e);
                ldsm4t(vl[g], sb + OFF_BLO + 2 * e);
            }
            #pragma unroll
            for (int mi = 0; mi < 2; mi++)
                #pragma unroll
                for (int ni = 0; ni < 4; ni++) {
                    int g = ni >> 1, ix = (ni & 1) * 2;
                    mma16816(c[mi][ni], ph[mi], vh[g][ix], vh[g][ix + 1]);
                    mma16816(c[mi][ni], ph[mi], vl[g][ix], vl[g][ix + 1]);
                    mma16816(c[mi][ni], pl[mi], vh[g][ix], vh[g][ix + 1]);
                }
        }
    }

    // ctx store straight from fragments
    float* ctxBase = ctx + ((size_t)b * SEQ + q0) * DIM;
    const int t4 = lane >> 2, q4 = lane & 3;
    #pragma unroll
    for (int mi = 0; mi < 2; mi++) {
        int rA = wm * 32 + mi * 16 + t4;
        #pragma unroll
        for (int ni = 0; ni < 4; ni++) {
            int col = wn * 32 + ni * 8 + 2 * q4;
            *(float2*)(ctxBase + (size_t)rA * DIM + col) =
                make_float2(c[mi][ni][0], c[mi][ni][1]);
            *(float2*)(ctxBase + (size_t)(rA + 8) * DIM + col) =
                make_float2(c[mi][ni][2], c[mi][ni][3]);
        }
    }
}

// ---------------------------------------------------------------------------
extern "C" void kernel_launch(void* const* d_in, const int* in_sizes, int n_in,
                              void* d_out, int out_size)
{
    const float* q = (const float*)d_in[0];
    const float* k = (const float*)d_in[1];
    const float* v = (const float*)d_in[2];

    const int B = in_sizes[0] / (SEQ * DIM);   // 32

    float* ctx  = (float*)d_out;                          // [B, S, D]
    float* attn = (float*)d_out + (size_t)B * SEQ * DIM;  // [B, S, S]

    cudaFuncSetAttribute(k1_scores,  cudaFuncAttributeMaxDynamicSharedMemorySize, SMEM1);
    cudaFuncSetAttribute(k2_context, cudaFuncAttributeMaxDynamicSharedMemorySize, SMEM2);

    dim3 grid(SEQ / MT, B);   // (16, 32) = 512 CTAs
    k1_scores <<<grid, 512, SMEM1>>>(q, k, attn);
    k2_context<<<grid, 512, SMEM2>>>(v, attn, ctx);
}

// round 15
// speedup vs baseline: 1.3481x; 1.3481x over previous
#include <cuda_runtime.h>
#include <cuda_bf16.h>
#include <stdint.h>

#define SEQ 2048
#define DIM 128
#define MT  128                 // q rows per CTA
#define NT  64                  // keys per tile
#define NTILES (SEQ / NT)       // 32
#define QBLKS (SEQ / MT)        // 16
#define RS  136                 // Q/K/V smem element stride (conflict-free ldmatrix)
#define PS  72                  // P smem element stride (conflict-free for stride 144B)

// ---- kernel A shared memory layout (bytes) ----
#define OFF_QHI 0
#define OFF_QLO 34816
#define OFF_KHI 69632           // 64 x 136 bf16 = 17408 per precision
#define OFF_KLO 87040
#define OFF_VHI 104448
#define OFF_VLO 121856
#define OFF_PHI 139264          // 128 x 72 bf16 = 18432 per precision
#define OFF_PLO 157696
#define OFF_STATM 176128        // 128 f32 running max
#define OFF_STATL (OFF_STATM + 512)
#define OFF_BM    (OFF_STATL + 512)   // broadcast new max
#define OFF_RSR   (OFF_BM + 512)      // exp(m_old - m_new) per row
#define OFF_RED   (OFF_RSR + 512)     // red[4][128]
#define SMEMA     (OFF_RED + 2048)    // 180224

#define MAXB 32
__device__ float g_stats[MAXB * SEQ * 2];                         // {m, 1/l}
__device__ float g_tilem[(size_t)MAXB * QBLKS * NTILES * MT];     // running max at tile t

// ---------------------------------------------------------------------------
__device__ __forceinline__ uint32_t smem_u32(const void* p) {
    uint32_t a;
    asm("{ .reg .u64 t; cvta.to.shared.u64 t, %1; cvt.u32.u64 %0, t; }" : "=r"(a) : "l"(p));
    return a;
}
__device__ __forceinline__ void ldsm4(uint32_t* r, uint32_t addr) {
    asm volatile("ldmatrix.sync.aligned.m8n8.x4.shared.b16 {%0,%1,%2,%3}, [%4];"
        : "=r"(r[0]), "=r"(r[1]), "=r"(r[2]), "=r"(r[3]) : "r"(addr));
}
__device__ __forceinline__ void ldsm4t(uint32_t* r, uint32_t addr) {
    asm volatile("ldmatrix.sync.aligned.m8n8.x4.trans.shared.b16 {%0,%1,%2,%3}, [%4];"
        : "=r"(r[0]), "=r"(r[1]), "=r"(r[2]), "=r"(r[3]) : "r"(addr));
}
__device__ __forceinline__ void mma16816(float* c, const uint32_t* a,
                                         uint32_t b0, uint32_t b1) {
    asm volatile(
        "mma.sync.aligned.m16n8k16.row.col.f32.bf16.bf16.f32 "
        "{%0,%1,%2,%3}, {%4,%5,%6,%7}, {%8,%9}, {%0,%1,%2,%3};"
        : "+f"(c[0]), "+f"(c[1]), "+f"(c[2]), "+f"(c[3])
        : "r"(a[0]), "r"(a[1]), "r"(a[2]), "r"(a[3]), "r"(b0), "r"(b1));
}
// split f32 pair into bf16 hi/lo pairs at element offset (even), stride-agnostic
__device__ __forceinline__ void split2(char* hi, char* lo, int eoff,
                                       float f0, float f1) {
    __nv_bfloat16 h0 = __float2bfloat16(f0);
    __nv_bfloat16 h1 = __float2bfloat16(f1);
    __nv_bfloat162 hp; hp.x = h0; hp.y = h1;
    __nv_bfloat162 lp;
    lp.x = __float2bfloat16(f0 - __bfloat162float(h0));
    lp.y = __float2bfloat16(f1 - __bfloat162float(h1));
    *reinterpret_cast<__nv_bfloat162*>(hi + 2 * eoff) = hp;
    *reinterpret_cast<__nv_bfloat162*>(lo + 2 * eoff) = lp;
}
__device__ __forceinline__ uint32_t pack_bf16x2(float f0, float f1) {
    __nv_bfloat162 h; h.x = __float2bfloat16(f0); h.y = __float2bfloat16(f1);
    return *reinterpret_cast<uint32_t*>(&h);
}

// ===========================================================================
// Kernel A: fused attention. Per CTA: 128 q rows; loop 32 kv tiles of 64.
// 16 warps = 4(wm) x 4(wn). Score warp tile 32q x 16kv; ctx warp tile 32q x 32d.
// ===========================================================================
__global__ void __launch_bounds__(512, 1) kA(
    const float* __restrict__ Q, const float* __restrict__ K,
    const float* __restrict__ V, float* __restrict__ ctx,
    float* __restrict__ attn)
{
    extern __shared__ char sm[];
    const uint32_t sb = smem_u32(sm);
    char* QHI = sm + OFF_QHI; char* QLO = sm + OFF_QLO;
    char* KHI = sm + OFF_KHI; char* KLO = sm + OFF_KLO;
    char* VHI = sm + OFF_VHI; char* VLO = sm + OFF_VLO;
    char* PHI = sm + OFF_PHI; char* PLO = sm + OFF_PLO;
    float* statm = (float*)(sm + OFF_STATM);
    float* statl = (float*)(sm + OFF_STATL);
    float* bm    = (float*)(sm + OFF_BM);
    float* rsr   = (float*)(sm + OFF_RSR);
    float* red   = (float*)(sm + OFF_RED);

    const int tid  = threadIdx.x;
    const int lane = tid & 31;
    const int w    = tid >> 5;
    const int wm   = w >> 2, wn = w & 3;
    const int b    = blockIdx.y;
    const int q0   = blockIdx.x * MT;
    const float scale = 0.08838834764831845f;   // 1/sqrt(128)

    const int aoff  = (lane & 15) * RS + ((lane & 16) >> 1);                 // A (Q)
    const int aoffP = (lane & 15) * PS + ((lane & 16) >> 1);                 // A (P)
    const int boff  = ((lane & 7) + ((lane & 16) >> 1)) * RS + (lane & 8);   // B (K)
    const int toff  = ((lane & 7) + (lane & 8)) * RS + ((lane & 16) >> 1);   // B trans (V)

    // Q tile -> scaled bf16 hi/lo (persistent)
    const float* Qg = Q + ((size_t)b * SEQ + q0) * DIM;
    for (int pi = tid; pi < MT * DIM / 2; pi += 512) {
        int r = pi >> 6, c2 = (pi & 63) * 2;
        float2 f = *(const float2*)(Qg + r * DIM + c2);
        split2(QHI, QLO, r * RS + c2, f.x * scale, f.y * scale);
    }
    if (tid < MT) { statm[tid] = -1e30f; statl[tid] = 0.f; }

    float* attnBase = attn + ((size_t)b * SEQ + q0) * SEQ;
    const float* Kg = K + (size_t)b * SEQ * DIM;
    const float* Vg = V + (size_t)b * SEQ * DIM;
    float* tmBase = g_tilem + (size_t)(b * QBLKS + blockIdx.x) * NTILES * MT;

    const int t4 = lane >> 2, q4 = lane & 3;

    float ctxa[2][4][4];                        // [mi][nj][4]  32 f32
    #pragma unroll
    for (int mi = 0; mi < 2; mi++)
        #pragma unroll
        for (int nj = 0; nj < 4; nj++)
            #pragma unroll
            for (int j = 0; j < 4; j++) ctxa[mi][nj][j] = 0.f;

    for (int t = 0; t < NTILES; t++) {
        const int k0 = t * NT;
        __syncthreads();                        // prev PV done; buffers free
        // K + V tiles (64 x 128 each) -> bf16 hi/lo
        for (int pi = tid; pi < NT * DIM / 2; pi += 512) {
            int r = pi >> 6, c2 = (pi & 63) * 2;
            float2 f = *(const float2*)(Kg + (size_t)(k0 + r) * DIM + c2);
            split2(KHI, KLO, r * RS + c2, f.x, f.y);
            float2 g = *(const float2*)(Vg + (size_t)(k0 + r) * DIM + c2);
            split2(VHI, VLO, r * RS + c2, g.x, g.y);
        }
        __syncthreads();

        // ---- score MMA: c = Q x K^T (3-term split) ----
        float c[2][2][4];
        #pragma unroll
        for (int mi = 0; mi < 2; mi++)
            #pragma unroll
            for (int ni = 0; ni < 2; ni++)
                #pragma unroll
                for (int j = 0; j < 4; j++) c[mi][ni][j] = 0.f;

        #pragma unroll
        for (int ks = 0; ks < 8; ks++) {
            const int k = ks * 16;
            uint32_t qh[2][4], ql[2][4], kh[4], kl[4];
            #pragma unroll
            for (int mi = 0; mi < 2; mi++) {
                int e = (wm * 32 + mi * 16) * RS + k + aoff;
                ldsm4(qh[mi], sb + OFF_QHI + 2 * e);
                ldsm4(ql[mi], sb + OFF_QLO + 2 * e);
            }
            {
                int e = (wn * 16) * RS + k + boff;
                ldsm4(kh, sb + OFF_KHI + 2 * e);
                ldsm4(kl, sb + OFF_KLO + 2 * e);
            }
            #pragma unroll
            for (int mi = 0; mi < 2; mi++)
                #pragma unroll
                for (int ni = 0; ni < 2; ni++) {
                    int ix = ni * 2;
                    mma16816(c[mi][ni], qh[mi], kh[ix], kh[ix + 1]);
                    mma16816(c[mi][ni], qh[mi], kl[ix], kl[ix + 1]);
                    mma16816(c[mi][ni], ql[mi], kh[ix], kh[ix + 1]);
                }
        }

        // ---- tile row-max ----
        #pragma unroll
        for (int mi = 0; mi < 2; mi++) {
            int rA = wm * 32 + mi * 16 + t4;
            float mA = -1e30f, mB = -1e30f;
            #pragma unroll
            for (int ni = 0; ni < 2; ni++) {
                mA = fmaxf(mA, fmaxf(c[mi][ni][0], c[mi][ni][1]));
                mB = fmaxf(mB, fmaxf(c[mi][ni][2], c[mi][ni][3]));
            }
            mA = fmaxf(mA, __shfl_xor_sync(0xffffffffu, mA, 1));
            mA = fmaxf(mA, __shfl_xor_sync(0xffffffffu, mA, 2));
            mB = fmaxf(mB, __shfl_xor_sync(0xffffffffu, mB, 1));
            mB = fmaxf(mB, __shfl_xor_sync(0xffffffffu, mB, 2));
            if (q4 == 0) { red[wn * 128 + rA] = mA; red[wn * 128 + rA + 8] = mB; }
        }
        __syncthreads();
        if (tid < MT) {
            float mt = fmaxf(fmaxf(red[tid], red[128 + tid]),
                             fmaxf(red[256 + tid], red[384 + tid]));
            float mnew = fmaxf(statm[tid], mt);
            bm[tid]  = mnew;
            rsr[tid] = __expf(statm[tid] - mnew);
            statm[tid] = mnew;
            tmBase[(size_t)t * MT + tid] = mnew;
        }
        __syncthreads();

        // ---- e = exp(c - m): write gmem (streaming) + P smem; sumexp; rescale ctx ----
        #pragma unroll
        for (int mi = 0; mi < 2; mi++) {
            int rA = wm * 32 + mi * 16 + t4;
            float mA = bm[rA], mB = bm[rA + 8];
            float sA = 0.f, sB = 0.f;
            #pragma unroll
            for (int ni = 0; ni < 2; ni++) {
                float e0 = __expf(c[mi][ni][0] - mA);
                float e1 = __expf(c[mi][ni][1] - mA);
                float e2 = __expf(c[mi][ni][2] - mB);
                float e3 = __expf(c[mi][ni][3] - mB);
                int kc  = wn * 16 + ni * 8 + 2 * q4;      // 0..63 within tile
                int col = k0 + kc;
                __stcs((float2*)(attnBase + (size_t)rA * SEQ + col), make_float2(e0, e1));
                __stcs((float2*)(attnBase + (size_t)(rA + 8) * SEQ + col), make_float2(e2, e3));
                // P hi/lo smem (stride PS)
                *(uint32_t*)(PHI + 2 * (rA * PS + kc)) = pack_bf16x2(e0, e1);
                *(uint32_t*)(PHI + 2 * ((rA + 8) * PS + kc)) = pack_bf16x2(e2, e3);
                __nv_bfloat16 h;
                h = __float2bfloat16(e0); float l0 = e0 - __bfloat162float(h);
                h = __float2bfloat16(e1); float l1 = e1 - __bfloat162float(h);
                *(uint32_t*)(PLO + 2 * (rA * PS + kc)) = pack_bf16x2(l0, l1);
                h = __float2bfloat16(e2); float l2 = e2 - __bfloat162float(h);
                h = __float2bfloat16(e3); float l3 = e3 - __bfloat162float(h);
                *(uint32_t*)(PLO + 2 * ((rA + 8) * PS + kc)) = pack_bf16x2(l2, l3);
                sA += e0 + e1;
                sB += e2 + e3;
            }
            sA += __shfl_xor_sync(0xffffffffu, sA, 1);
            sA += __shfl_xor_sync(0xffffffffu, sA, 2);
            sB += __shfl_xor_sync(0xffffffffu, sB, 1);
            sB += __shfl_xor_sync(0xffffffffu, sB, 2);
            if (q4 == 0) { red[wn * 128 + rA] = sA; red[wn * 128 + rA + 8] = sB; }
            // rescale ctx accumulators (rows match score rows)
            float rsA = rsr[rA], rsB = rsr[rA + 8];
            #pragma unroll
            for (int nj = 0; nj < 4; nj++) {
                ctxa[mi][nj][0] *= rsA; ctxa[mi][nj][1] *= rsA;
                ctxa[mi][nj][2] *= rsB; ctxa[mi][nj][3] *= rsB;
            }
        }
        __syncthreads();                        // P smem + sumexp partials ready
        if (tid < MT) {
            statl[tid] = statl[tid] * rsr[tid] +
                         red[tid] + red[128 + tid] + red[256 + tid] + red[384 + tid];
        }

        // ---- PV MMA: ctx += P x V (3-term split) ----
        #pragma unroll
        for (int ks2 = 0; ks2 < 4; ks2++) {
            const int k = ks2 * 16;
            uint32_t ph[2][4], pl[2][4], vh[2][4], vl[2][4];
            #pragma unroll
            for (int mi = 0; mi < 2; mi++) {
                int e = (wm * 32 + mi * 16) * PS + k + aoffP;
                ldsm4(ph[mi], sb + OFF_PHI + 2 * e);
                ldsm4(pl[mi], sb + OFF_PLO + 2 * e);
            }
            #pragma unroll
            for (int g = 0; g < 2; g++) {
                int e = k * RS + (wn * 32 + g * 16) + toff;
                ldsm4t(vh[g], sb + OFF_VHI + 2 * e);
                ldsm4t(vl[g], sb + OFF_VLO + 2 * e);
            }
            #pragma unroll
            for (int mi = 0; mi < 2; mi++)
                #pragma unroll
                for (int nj = 0; nj < 4; nj++) {
                    int g = nj >> 1, ix = (nj & 1) * 2;
                    mma16816(ctxa[mi][nj], ph[mi], vh[g][ix], vh[g][ix + 1]);
                    mma16816(ctxa[mi][nj], ph[mi], vl[g][ix], vl[g][ix + 1]);
                    mma16816(ctxa[mi][nj], pl[mi], vh[g][ix], vh[g][ix + 1]);
                }
        }
    }

    __syncthreads();
    if (tid < MT) {
        float il = 1.f / statl[tid];
        statl[tid] = il;
        int row = b * SEQ + q0 + tid;
        g_stats[row * 2]     = statm[tid];
        g_stats[row * 2 + 1] = il;
    }
    __syncthreads();

    // ---- ctx store ----
    float* ctxBase = ctx + ((size_t)b * SEQ + q0) * DIM;
    #pragma unroll
    for (int mi = 0; mi < 2; mi++) {
        int rA = wm * 32 + mi * 16 + t4;
        float ilA = statl[rA], ilB = statl[rA + 8];
        #pragma unroll
        for (int nj = 0; nj < 4; nj++) {
            int col = wn * 32 + nj * 8 + 2 * q4;
            *(float2*)(ctxBase + (size_t)rA * DIM + col) =
                make_float2(ctxa[mi][nj][0] * ilA, ctxa[mi][nj][1] * ilA);
            *(float2*)(ctxBase + (size_t)(rA + 8) * DIM + col) =
                make_float2(ctxa[mi][nj][2] * ilB, ctxa[mi][nj][3] * ilB);
        }
    }
}

// ===========================================================================
// Kernel B: streaming rescale  p = e * exp(m_t - m) / l
// Block = 256 threads, 8 rows; pure float4 stream.
// ===========================================================================
__global__ void __launch_bounds__(256) kB(float* __restrict__ attn)
{
    __shared__ float fac[8][NTILES];
    const int tid = threadIdx.x;
    const int b   = blockIdx.y;
    const int r0  = blockIdx.x * 8;

    {
        int rr = tid >> 5, t = tid & 31;        // 256 threads = 8 x 32 exactly
        int row = r0 + rr;
        int gr  = b * SEQ + row;
        float m  = g_stats[gr * 2];
        float il = g_stats[gr * 2 + 1];
        int qblk = row >> 7, ri = row & 127;
        float mt = g_tilem[(size_t)((b * QBLKS + qblk) * NTILES + t) * MT + ri];
        fac[rr][t] = __expf(mt - m) * il;
    }
    __syncthreads();

    float* base = attn + ((size_t)b * SEQ + r0) * SEQ;
    #pragma unroll 4
    for (int it = 0; it < 16; it++) {
        int idx = it * 256 + tid;               // float4 index over 8x2048
        int rr  = idx >> 9;
        int c4  = idx & 511;
        float4* p = (float4*)(base + (size_t)rr * SEQ) + c4;
        float4 e = __ldcs(p);
        float f = fac[rr][c4 >> 4];             // tile = (c4*4)>>6
        e.x *= f; e.y *= f; e.z *= f; e.w *= f;
        __stcs(p, e);
    }
}

// ---------------------------------------------------------------------------
extern "C" void kernel_launch(void* const* d_in, const int* in_sizes, int n_in,
                              void* d_out, int out_size)
{
    const float* q = (const float*)d_in[0];
    const float* k = (const float*)d_in[1];
    const float* v = (const float*)d_in[2];

    const int B = in_sizes[0] / (SEQ * DIM);   // 32

    float* ctx  = (float*)d_out;                          // [B, S, D]
    float* attn = (float*)d_out + (size_t)B * SEQ * DIM;  // [B, S, S]

    cudaFuncSetAttribute(kA, cudaFuncAttributeMaxDynamicSharedMemorySize, SMEMA);

    dim3 gridA(SEQ / MT, B);    // (16, 32)
    kA<<<gridA, 512, SMEMA>>>(q, k, v, ctx, attn);

    dim3 gridB(SEQ / 8, B);     // (256, 32)
    kB<<<gridB, 256>>>(attn);
}

// round 16
// speedup vs baseline: 1.5228x; 1.1296x over previous
#include <cuda_runtime.h>
#include <cuda_bf16.h>
#include <stdint.h>

#define SEQ 2048
#define DIM 128
#define MT  128                 // q rows per CTA
#define NT  64                  // keys per tile
#define NTILES (SEQ / NT)       // 32
#define QBLKS (SEQ / MT)        // 16
#define RS  136                 // smem element stride (conflict-free ldmatrix)

// ---- kernel A shared memory layout (bytes) ----
#define OFF_QHI  0              // 128 x 136 bf16 = 34816
#define OFF_QLO  34816
#define OFF_KHI  69632          // 64 x 136 bf16 = 17408
#define OFF_KLO  87040
#define OFF_VHI  104448
#define OFF_VLO  121856
#define OFF_KRAW 139264         // 64 x 128 f32 = 32768 (cp.async staging)
#define OFF_VRAW 172032
#define SMEMA    204800

#define MAXB 32
__device__ float g_stats[MAXB * SEQ * 2];                         // {m, 1/l}
__device__ float g_tilem[(size_t)MAXB * QBLKS * NTILES * MT];     // running max at tile t

// ---------------------------------------------------------------------------
__device__ __forceinline__ uint32_t smem_u32(const void* p) {
    uint32_t a;
    asm("{ .reg .u64 t; cvta.to.shared.u64 t, %1; cvt.u32.u64 %0, t; }" : "=r"(a) : "l"(p));
    return a;
}
__device__ __forceinline__ void ldsm4(uint32_t* r, uint32_t addr) {
    asm volatile("ldmatrix.sync.aligned.m8n8.x4.shared.b16 {%0,%1,%2,%3}, [%4];"
        : "=r"(r[0]), "=r"(r[1]), "=r"(r[2]), "=r"(r[3]) : "r"(addr));
}
__device__ __forceinline__ void ldsm4t(uint32_t* r, uint32_t addr) {
    asm volatile("ldmatrix.sync.aligned.m8n8.x4.trans.shared.b16 {%0,%1,%2,%3}, [%4];"
        : "=r"(r[0]), "=r"(r[1]), "=r"(r[2]), "=r"(r[3]) : "r"(addr));
}
__device__ __forceinline__ void mma16816(float* c, const uint32_t* a,
                                         uint32_t b0, uint32_t b1) {
    asm volatile(
        "mma.sync.aligned.m16n8k16.row.col.f32.bf16.bf16.f32 "
        "{%0,%1,%2,%3}, {%4,%5,%6,%7}, {%8,%9}, {%0,%1,%2,%3};"
        : "+f"(c[0]), "+f"(c[1]), "+f"(c[2]), "+f"(c[3])
        : "r"(a[0]), "r"(a[1]), "r"(a[2]), "r"(a[3]), "r"(b0), "r"(b1));
}
__device__ __forceinline__ void cpa16(uint32_t saddr, const void* g) {
    asm volatile("cp.async.cg.shared.global [%0], [%1], 16;" :: "r"(saddr), "l"(g));
}
#define CP_COMMIT() asm volatile("cp.async.commit_group;" ::: "memory")
#define CP_WAIT0()  asm volatile("cp.async.wait_group 0;" ::: "memory")

__device__ __forceinline__ void split2(char* hi, char* lo, int eoff,
                                       float f0, float f1) {
    __nv_bfloat16 h0 = __float2bfloat16(f0);
    __nv_bfloat16 h1 = __float2bfloat16(f1);
    __nv_bfloat162 hp; hp.x = h0; hp.y = h1;
    __nv_bfloat162 lp;
    lp.x = __float2bfloat16(f0 - __bfloat162float(h0));
    lp.y = __float2bfloat16(f1 - __bfloat162float(h1));
    *reinterpret_cast<__nv_bfloat162*>(hi + 2 * eoff) = hp;
    *reinterpret_cast<__nv_bfloat162*>(lo + 2 * eoff) = lp;
}
__device__ __forceinline__ uint32_t pack_hi2(float f0, float f1) {
    __nv_bfloat162 h; h.x = __float2bfloat16(f0); h.y = __float2bfloat16(f1);
    return *reinterpret_cast<uint32_t*>(&h);
}
__device__ __forceinline__ uint32_t pack_lo2(float f0, float f1) {
    float l0 = f0 - __bfloat162float(__float2bfloat16(f0));
    float l1 = f1 - __bfloat162float(__float2bfloat16(f1));
    __nv_bfloat162 h; h.x = __float2bfloat16(l0); h.y = __float2bfloat16(l1);
    return *reinterpret_cast<uint32_t*>(&h);
}

// ===========================================================================
// Kernel A: fused FA2-style attention. 256 threads = 8 warps, each owns 16 q
// rows (full 64-key score stripe + full 128-d ctx stripe; P stays in regs).
// ===========================================================================
__global__ void __launch_bounds__(256, 1) kA(
    const float* __restrict__ Q, const float* __restrict__ K,
    const float* __restrict__ V, float* __restrict__ ctx,
    float* __restrict__ attn)
{
    extern __shared__ char sm[];
    const uint32_t sb = smem_u32(sm);
    char* QHI = sm + OFF_QHI; char* QLO = sm + OFF_QLO;
    char* KHI = sm + OFF_KHI; char* KLO = sm + OFF_KLO;
    char* VHI = sm + OFF_VHI; char* VLO = sm + OFF_VLO;

    const int tid  = threadIdx.x;
    const int lane = tid & 31;
    const int w    = tid >> 5;
    const int qrow = w * 16;                // warp's q-row base within CTA
    const int t4   = lane >> 2, q4 = lane & 3;
    const int b    = blockIdx.y;
    const int q0   = blockIdx.x * MT;
    const float scale = 0.08838834764831845f;   // 1/sqrt(128)

    const int aoff = (lane & 15) * RS + ((lane & 16) >> 1);                 // A
    const int boff = ((lane & 7) + ((lane & 16) >> 1)) * RS + (lane & 8);   // B (K)
    const int toff = ((lane & 7) + (lane & 8)) * RS + ((lane & 16) >> 1);   // B^T (V)

    const float* Kg = K + (size_t)b * SEQ * DIM;
    const float* Vg = V + (size_t)b * SEQ * DIM;
    float* attnBase = attn + ((size_t)b * SEQ + q0) * SEQ;
    float* tmBase = g_tilem + (size_t)(b * QBLKS + blockIdx.x) * NTILES * MT;

    // ---- prologue: cp.async stage tile 0, convert Q while it flies ----
    {
        const float4* kg4 = (const float4*)Kg;
        const float4* vg4 = (const float4*)Vg;
        #pragma unroll
        for (int i = 0; i < 8; i++) {
            int idx = i * 256 + tid;            // float4 index, 2048 total
            cpa16(sb + OFF_KRAW + idx * 16, kg4 + idx);
            cpa16(sb + OFF_VRAW + idx * 16, vg4 + idx);
        }
        CP_COMMIT();
    }
    const float* Qg = Q + ((size_t)b * SEQ + q0) * DIM;
    for (int pi = tid; pi < MT * DIM / 2; pi += 256) {
        int r = pi >> 6, c2 = (pi & 63) * 2;
        float2 f = *(const float2*)(Qg + r * DIM + c2);
        split2(QHI, QLO, r * RS + c2, f.x * scale, f.y * scale);
    }

    float mrA = -1e30f, mrB = -1e30f, lrA = 0.f, lrB = 0.f;
    float ctxa[16][4];
    #pragma unroll
    for (int nj = 0; nj < 16; nj++)
        #pragma unroll
        for (int j = 0; j < 4; j++) ctxa[nj][j] = 0.f;

    CP_WAIT0();
    __syncthreads();

    for (int t = 0; t < NTILES; t++) {
        const int k0 = t * NT;

        // ---- convert raw(t) -> bf16 hi/lo split ----
        for (int pi = tid; pi < NT * DIM / 2; pi += 256) {
            int r = pi >> 6, c2 = (pi & 63) * 2;
            float2 f = *(const float2*)(sm + OFF_KRAW + (r * DIM + c2) * 4);
            split2(KHI, KLO, r * RS + c2, f.x, f.y);
            float2 g = *(const float2*)(sm + OFF_VRAW + (r * DIM + c2) * 4);
            split2(VHI, VLO, r * RS + c2, g.x, g.y);
        }
        __syncthreads();

        // ---- issue cp.async for tile t+1 (overlaps MMA below) ----
        if (t + 1 < NTILES) {
            const float4* kg4 = (const float4*)(Kg + (size_t)(k0 + NT) * DIM);
            const float4* vg4 = (const float4*)(Vg + (size_t)(k0 + NT) * DIM);
            #pragma unroll
            for (int i = 0; i < 8; i++) {
                int idx = i * 256 + tid;
                cpa16(sb + OFF_KRAW + idx * 16, kg4 + idx);
                cpa16(sb + OFF_VRAW + idx * 16, vg4 + idx);
            }
            CP_COMMIT();
        }

        // ---- score MMA: c = Q x K^T  (16q x 64k, 3-term split) ----
        float c[8][4];
        #pragma unroll
        for (int ni = 0; ni < 8; ni++)
            #pragma unroll
            for (int j = 0; j < 4; j++) c[ni][j] = 0.f;

        #pragma unroll
        for (int ks = 0; ks < 8; ks++) {
            const int k = ks * 16;
            uint32_t qh[4], ql[4];
            ldsm4(qh, sb + OFF_QHI + 2 * (qrow * RS + k + aoff));
            ldsm4(ql, sb + OFF_QLO + 2 * (qrow * RS + k + aoff));
            #pragma unroll
            for (int kb = 0; kb < 4; kb++) {
                uint32_t kh[4], kl[4];
                ldsm4(kh, sb + OFF_KHI + 2 * ((kb * 16) * RS + k + boff));
                ldsm4(kl, sb + OFF_KLO + 2 * ((kb * 16) * RS + k + boff));
                mma16816(c[kb * 2],     qh, kh[0], kh[1]);
                mma16816(c[kb * 2],     qh, kl[0], kl[1]);
                mma16816(c[kb * 2],     ql, kh[0], kh[1]);
                mma16816(c[kb * 2 + 1], qh, kh[2], kh[3]);
                mma16816(c[kb * 2 + 1], qh, kl[2], kl[3]);
                mma16816(c[kb * 2 + 1], ql, kh[2], kh[3]);
            }
        }

        // ---- warp-local online softmax ----
        float mA = -1e30f, mB = -1e30f;
        #pragma unroll
        for (int ni = 0; ni < 8; ni++) {
            mA = fmaxf(mA, fmaxf(c[ni][0], c[ni][1]));
            mB = fmaxf(mB, fmaxf(c[ni][2], c[ni][3]));
        }
        mA = fmaxf(mA, __shfl_xor_sync(0xffffffffu, mA, 1));
        mA = fmaxf(mA, __shfl_xor_sync(0xffffffffu, mA, 2));
        mB = fmaxf(mB, __shfl_xor_sync(0xffffffffu, mB, 1));
        mB = fmaxf(mB, __shfl_xor_sync(0xffffffffu, mB, 2));
        float mnA = fmaxf(mrA, mA), mnB = fmaxf(mrB, mB);
        float rsA = __expf(mrA - mnA), rsB = __expf(mrB - mnB);
        mrA = mnA; mrB = mnB;
        if (q4 == 0) {
            tmBase[t * MT + qrow + t4]     = mnA;
            tmBase[t * MT + qrow + t4 + 8] = mnB;
        }

        float sA = 0.f, sB = 0.f;
        #pragma unroll
        for (int ni = 0; ni < 8; ni++) {
            float e0 = __expf(c[ni][0] - mnA);
            float e1 = __expf(c[ni][1] - mnA);
            float e2 = __expf(c[ni][2] - mnB);
            float e3 = __expf(c[ni][3] - mnB);
            c[ni][0] = e0; c[ni][1] = e1; c[ni][2] = e2; c[ni][3] = e3;
            sA += e0 + e1; sB += e2 + e3;
            int col = k0 + ni * 8 + 2 * q4;
            __stcs((float2*)(attnBase + (size_t)(qrow + t4) * SEQ + col), make_float2(e0, e1));
            __stcs((float2*)(attnBase + (size_t)(qrow + t4 + 8) * SEQ + col), make_float2(e2, e3));
        }
        sA += __shfl_xor_sync(0xffffffffu, sA, 1);
        sA += __shfl_xor_sync(0xffffffffu, sA, 2);
        sB += __shfl_xor_sync(0xffffffffu, sB, 1);
        sB += __shfl_xor_sync(0xffffffffu, sB, 2);
        lrA = lrA * rsA + sA;
        lrB = lrB * rsB + sB;

        // ---- rescale ctx accumulators ----
        #pragma unroll
        for (int nj = 0; nj < 16; nj++) {
            ctxa[nj][0] *= rsA; ctxa[nj][1] *= rsA;
            ctxa[nj][2] *= rsB; ctxa[nj][3] *= rsB;
        }

        // ---- P fragments in registers (hi/lo) ----
        uint32_t phi[4][4], plo[4][4];
        #pragma unroll
        for (int ks2 = 0; ks2 < 4; ks2++) {
            int n0 = 2 * ks2, n1 = 2 * ks2 + 1;
            phi[ks2][0] = pack_hi2(c[n0][0], c[n0][1]);
            phi[ks2][1] = pack_hi2(c[n0][2], c[n0][3]);
            phi[ks2][2] = pack_hi2(c[n1][0], c[n1][1]);
            phi[ks2][3] = pack_hi2(c[n1][2], c[n1][3]);
            plo[ks2][0] = pack_lo2(c[n0][0], c[n0][1]);
            plo[ks2][1] = pack_lo2(c[n0][2], c[n0][3]);
            plo[ks2][2] = pack_lo2(c[n1][0], c[n1][1]);
            plo[ks2][3] = pack_lo2(c[n1][2], c[n1][3]);
        }

        // ---- PV MMA: ctx += P x V  (16q x 128d over 64 keys, 3-term) ----
        #pragma unroll
        for (int ks2 = 0; ks2 < 4; ks2++) {
            const int k = ks2 * 16;
            #pragma unroll
            for (int dg = 0; dg < 8; dg++) {
                uint32_t vh[4], vl[4];
                ldsm4t(vh, sb + OFF_VHI + 2 * (k * RS + dg * 16 + toff));
                ldsm4t(vl, sb + OFF_VLO + 2 * (k * RS + dg * 16 + toff));
                mma16816(ctxa[dg * 2],     phi[ks2], vh[0], vh[1]);
                mma16816(ctxa[dg * 2],     phi[ks2], vl[0], vl[1]);
                mma16816(ctxa[dg * 2],     plo[ks2], vh[0], vh[1]);
                mma16816(ctxa[dg * 2 + 1], phi[ks2], vh[2], vh[3]);
                mma16816(ctxa[dg * 2 + 1], phi[ks2], vl[2], vl[3]);
                mma16816(ctxa[dg * 2 + 1], plo[ks2], vh[2], vh[3]);
            }
        }

        if (t + 1 < NTILES) CP_WAIT0();
        __syncthreads();                        // split bufs free + raw(t+1) visible
    }

    // ---- final stats + ctx store ----
    float ilA = 1.f / lrA, ilB = 1.f / lrB;
    if (q4 == 0) {
        int rA = b * SEQ + q0 + qrow + t4;
        g_stats[rA * 2] = mrA;     g_stats[rA * 2 + 1] = ilA;
        g_stats[(rA + 8) * 2] = mrB; g_stats[(rA + 8) * 2 + 1] = ilB;
    }
    float* ctxBase = ctx + ((size_t)b * SEQ + q0) * DIM;
    #pragma unroll
    for (int nj = 0; nj < 16; nj++) {
        int col = nj * 8 + 2 * q4;
        *(float2*)(ctxBase + (size_t)(qrow + t4) * DIM + col) =
            make_float2(ctxa[nj][0] * ilA, ctxa[nj][1] * ilA);
        *(float2*)(ctxBase + (size_t)(qrow + t4 + 8) * DIM + col) =
            make_float2(ctxa[nj][2] * ilB, ctxa[nj][3] * ilB);
    }
}

// ===========================================================================
// Kernel B: streaming rescale  p = e * exp(m_t - m) / l   (unchanged, ~80% BW)
// ===========================================================================
__global__ void __launch_bounds__(256) kB(float* __restrict__ attn)
{
    __shared__ float fac[8][NTILES];
    const int tid = threadIdx.x;
    const int b   = blockIdx.y;
    const int r0  = blockIdx.x * 8;

    {
        int rr = tid >> 5, t = tid & 31;        // 256 threads = 8 x 32
        int row = r0 + rr;
        int gr  = b * SEQ + row;
        float m  = g_stats[gr * 2];
        float il = g_stats[gr * 2 + 1];
        int qblk = row >> 7, ri = row & 127;
        float mt = g_tilem[(size_t)((b * QBLKS + qblk) * NTILES + t) * MT + ri];
        fac[rr][t] = __expf(mt - m) * il;
    }
    __syncthreads();

    float* base = attn + ((size_t)b * SEQ + r0) * SEQ;
    #pragma unroll 4
    for (int it = 0; it < 16; it++) {
        int idx = it * 256 + tid;               // float4 index over 8x2048
        int rr  = idx >> 9;
        int c4  = idx & 511;
        float4* p = (float4*)(base + (size_t)rr * SEQ) + c4;
        float4 e = __ldcs(p);
        float f = fac[rr][c4 >> 4];
        e.x *= f; e.y *= f; e.z *= f; e.w *= f;
        __stcs(p, e);
    }
}

// ---------------------------------------------------------------------------
extern "C" void kernel_launch(void* const* d_in, const int* in_sizes, int n_in,
                              void* d_out, int out_size)
{
    const float* q = (const float*)d_in[0];
    const float* k = (const float*)d_in[1];
    const float* v = (const float*)d_in[2];

    const int B = in_sizes[0] / (SEQ * DIM);   // 32

    float* ctx  = (float*)d_out;                          // [B, S, D]
    float* attn = (float*)d_out + (size_t)B * SEQ * DIM;  // [B, S, S]

    cudaFuncSetAttribute(kA, cudaFuncAttributeMaxDynamicSharedMemorySize, SMEMA);

    dim3 gridA(SEQ / MT, B);    // (16, 32)
    kA<<<gridA, 256, SMEMA>>>(q, k, v, ctx, attn);

    dim3 gridB(SEQ / 8, B);     // (256, 32)
    kB<<<gridB, 256>>>(attn);
}